// round 1
// baseline (speedup 1.0000x reference)
#include <cuda_runtime.h>
#include <math.h>

#define BSZ 8
#define LSEQ 2048
#define DM 512
#define NS 64
#define EMB 512

// Scratch (allocation-free rule: __device__ globals)
__device__ float g_xn[BSZ * LSEQ * DM];    // LayerNorm output, (B,L,d)
__device__ float g_y2[BSZ * LSEQ * DM];    // post-conv, post-FiLM, (B,L,d)
__device__ float g_film[BSZ * 2 * DM];     // FiLM scale/shift

// ---------------------------------------------------------------------------
// Kernel 1: LayerNorm over last dim (512). One block per (b,l) row.
// 128 threads, each handles one float4 (512 floats / row).
// ---------------------------------------------------------------------------
__global__ void ln_kernel(const float* __restrict__ x,
                          const float* __restrict__ gamma,
                          const float* __restrict__ beta) {
    const int row = blockIdx.x;  // b*L + l
    const int t = threadIdx.x;   // 0..127
    const float4* xr = (const float4*)(x + (size_t)row * DM);
    float4 v = xr[t];
    float s  = v.x + v.y + v.z + v.w;
    float ss = v.x * v.x + v.y * v.y + v.z * v.z + v.w * v.w;

    __shared__ float sh[8];
    #pragma unroll
    for (int o = 16; o; o >>= 1) {
        s  += __shfl_xor_sync(0xffffffffu, s, o);
        ss += __shfl_xor_sync(0xffffffffu, ss, o);
    }
    int w = t >> 5;
    if ((t & 31) == 0) { sh[w] = s; sh[4 + w] = ss; }
    __syncthreads();
    float S  = sh[0] + sh[1] + sh[2] + sh[3];
    float SS = sh[4] + sh[5] + sh[6] + sh[7];

    const float inv = 1.0f / (float)DM;
    float mu = S * inv;
    float var = SS * inv - mu * mu;
    float rs = rsqrtf(var + 1e-5f);

    float4 g4 = ((const float4*)gamma)[t];
    float4 b4 = ((const float4*)beta)[t];
    float4 o4;
    o4.x = (v.x - mu) * rs * g4.x + b4.x;
    o4.y = (v.y - mu) * rs * g4.y + b4.y;
    o4.z = (v.z - mu) * rs * g4.z + b4.z;
    o4.w = (v.w - mu) * rs * g4.w + b4.w;
    ((float4*)(g_xn + (size_t)row * DM))[t] = o4;
}

// ---------------------------------------------------------------------------
// Kernel 2: FiLM params: film[b,j] = b_film[j] + sum_e silu(emb[b,e])*W_film[j,e]
// One block per b, 256 threads.
// ---------------------------------------------------------------------------
__global__ void film_kernel(const float* __restrict__ emb,
                            const float* __restrict__ Wf,
                            const float* __restrict__ bf) {
    __shared__ float se[EMB];
    const int b = blockIdx.x;
    for (int i = threadIdx.x; i < EMB; i += blockDim.x) {
        float e = emb[b * EMB + i];
        se[i] = e / (1.0f + expf(-e));
    }
    __syncthreads();
    for (int j = threadIdx.x; j < 2 * DM; j += blockDim.x) {
        const float4* wr = (const float4*)(Wf + (size_t)j * EMB);
        const float4* sr = (const float4*)se;
        float acc = bf[j];
        #pragma unroll 4
        for (int q = 0; q < EMB / 4; q++) {
            float4 w = wr[q], sv = sr[q];
            acc += w.x * sv.x + w.y * sv.y + w.z * sv.z + w.w * sv.w;
        }
        g_film[b * 2 * DM + j] = acc;
    }
}

// ---------------------------------------------------------------------------
// Kernel 3: S4D diagonal complex scan + D-skip + FiLM, fused.
//   s_n[l] = Abar_n * s_n[l-1] + x[l];  y[l] = dt*Re(sum_n Cc_n * s_n[l])
// Layout: 16 lanes per (b,d) "group", each lane holds 4 of the 64 states.
// Block = 128 threads = 8 groups = 8 consecutive d (same b).
// x staged through double-buffered SMEM (one 32B sector per l per block).
// ---------------------------------------------------------------------------
__global__ void scan_kernel(const float* __restrict__ A_real,
                            const float* __restrict__ A_imag,
                            const float* __restrict__ Cp,
                            const float* __restrict__ log_dt,
                            const float* __restrict__ B_ssm,
                            const float* __restrict__ D_skip) {
    const int t = threadIdx.x;        // 0..127
    const int grp = t >> 4;           // 0..7  (which d within block)
    const int g = t & 15;             // lane within group
    const int gid = blockIdx.x * 8 + grp;
    const int b = gid >> 9;           // /512
    const int d = gid & 511;
    const int d0 = (blockIdx.x * 8) & 511;

    const float dt = expf(log_dt[d]);
    float Abr[4], Abi[4], Ccr[4], Cci[4], sr[4], si[4];
    #pragma unroll
    for (int k = 0; k < 4; k++) {
        int n = g * 4 + k;
        float ar = dt * A_real[d * NS + n];
        float ai = dt * A_imag[d * NS + n];
        float er = expf(ar), sb, cb;
        sincosf(ai, &sb, &cb);
        Abr[k] = er * cb;
        Abi[k] = er * sb;
        float bs = B_ssm[d * NS + n];
        Ccr[k] = Cp[(d * NS + n) * 2 + 0] * bs;
        Cci[k] = Cp[(d * NS + n) * 2 + 1] * bs;
        sr[k] = 0.0f; si[k] = 0.0f;
    }
    const float dsk = D_skip[d];
    const float mult  = 1.0f + g_film[b * 2 * DM + d];
    const float shift = g_film[b * 2 * DM + DM + d];

    __shared__ float sx[2][64][8];
    const float* xbase = g_xn + (size_t)b * LSEQ * DM + d0;
    float* ybase = g_y2 + (size_t)b * LSEQ * DM + d;

    const int ll = t >> 1, half = t & 1;  // load mapping: 64 l x 2 halves
    // preload chunk 0
    {
        float4 v = *(const float4*)(xbase + (size_t)ll * DM + half * 4);
        *(float4*)&sx[0][ll][half * 4] = v;
    }
    __syncthreads();

    const int myd = grp;
    for (int chunk = 0; chunk < LSEQ / 64; chunk++) {
        const int cur = chunk & 1;
        float4 nld;
        const bool more = (chunk + 1 < LSEQ / 64);
        if (more) {
            nld = *(const float4*)(xbase + (size_t)((chunk + 1) * 64 + ll) * DM + half * 4);
        }
        #pragma unroll 4
        for (int i = 0; i < 64; i++) {
            float xv = sx[cur][i][myd];
            float tsum = 0.0f;
            #pragma unroll
            for (int k = 0; k < 4; k++) {
                float nr = Abr[k] * sr[k] - Abi[k] * si[k] + xv;
                float ni = Abr[k] * si[k] + Abi[k] * sr[k];
                sr[k] = nr; si[k] = ni;
                tsum += Ccr[k] * nr - Cci[k] * ni;
            }
            #pragma unroll
            for (int o = 8; o; o >>= 1)
                tsum += __shfl_xor_sync(0xffffffffu, tsum, o);
            if (g == 0) {
                float out = dt * tsum + dsk * xv;
                ybase[(size_t)(chunk * 64 + i) * DM] = out * mult + shift;
            }
        }
        if (more) {
            *(float4*)&sx[cur ^ 1][ll][half * 4] = nld;
        }
        __syncthreads();
    }
}

// ---------------------------------------------------------------------------
// Kernel 4: out_proj GEMM (M=16384, K=512) with paired a/g columns + GLU +
// residual, fused epilogue. Tile 128x64(x2), BK=16, 256 threads, 8x4x2/thread.
// ---------------------------------------------------------------------------
#define GBM 128
#define GBN 64
#define GBK 16

__global__ void __launch_bounds__(256, 2)
gemm_glu_kernel(const float* __restrict__ W,
                const float* __restrict__ bo,
                const float* __restrict__ resid,
                float* __restrict__ out) {
    const int m0 = blockIdx.x * GBM;
    const int c0 = blockIdx.y * GBN;

    __shared__ float As[GBK][GBM];
    __shared__ float Ba[GBK][GBN];
    __shared__ float Bg[GBK][GBN];

    const int tid = threadIdx.x;
    const int tx = tid & 15;   // 0..15 -> 4 cols each
    const int ty = tid >> 4;   // 0..15 -> 8 rows each

    float acc_a[8][4];
    float acc_g[8][4];
    #pragma unroll
    for (int r = 0; r < 8; r++)
        #pragma unroll
        for (int c = 0; c < 4; c++) { acc_a[r][c] = 0.0f; acc_g[r][c] = 0.0f; }

    for (int kt = 0; kt < DM; kt += GBK) {
        // load A tile (y2): 128 rows x 16 k = 512 float4, 2 per thread
        #pragma unroll
        for (int i = 0; i < 2; i++) {
            int q = tid + i * 256;
            int m = q >> 2, kq = q & 3;
            float4 v = *(const float4*)(g_y2 + (size_t)(m0 + m) * DM + kt + kq * 4);
            As[kq * 4 + 0][m] = v.x;
            As[kq * 4 + 1][m] = v.y;
            As[kq * 4 + 2][m] = v.z;
            As[kq * 4 + 3][m] = v.w;
        }
        // load B tiles (W rows c0..c0+63 and c0+512..): 1 float4 each
        {
            int r = tid >> 2, kq = tid & 3;
            float4 va = *(const float4*)(W + (size_t)(c0 + r) * DM + kt + kq * 4);
            Ba[kq * 4 + 0][r] = va.x;
            Ba[kq * 4 + 1][r] = va.y;
            Ba[kq * 4 + 2][r] = va.z;
            Ba[kq * 4 + 3][r] = va.w;
            float4 vg = *(const float4*)(W + (size_t)(DM + c0 + r) * DM + kt + kq * 4);
            Bg[kq * 4 + 0][r] = vg.x;
            Bg[kq * 4 + 1][r] = vg.y;
            Bg[kq * 4 + 2][r] = vg.z;
            Bg[kq * 4 + 3][r] = vg.w;
        }
        __syncthreads();

        #pragma unroll
        for (int k = 0; k < GBK; k++) {
            float4 a0 = *(float4*)&As[k][ty * 8];
            float4 a1 = *(float4*)&As[k][ty * 8 + 4];
            float4 ba = *(float4*)&Ba[k][tx * 4];
            float4 bg = *(float4*)&Bg[k][tx * 4];
            float ar[8] = {a0.x, a0.y, a0.z, a0.w, a1.x, a1.y, a1.z, a1.w};
            float bca[4] = {ba.x, ba.y, ba.z, ba.w};
            float bcg[4] = {bg.x, bg.y, bg.z, bg.w};
            #pragma unroll
            for (int r = 0; r < 8; r++) {
                #pragma unroll
                for (int c = 0; c < 4; c++) {
                    acc_a[r][c] += ar[r] * bca[c];
                    acc_g[r][c] += ar[r] * bcg[c];
                }
            }
        }
        __syncthreads();
    }

    // epilogue: a*sigmoid(g) + residual
    #pragma unroll
    for (int r = 0; r < 8; r++) {
        int m = m0 + ty * 8 + r;
        #pragma unroll
        for (int c = 0; c < 4; c++) {
            int i = c0 + tx * 4 + c;
            float a  = acc_a[r][c] + bo[i];
            float gg = acc_g[r][c] + bo[DM + i];
            out[(size_t)m * DM + i] =
                resid[(size_t)m * DM + i] + a * (1.0f / (1.0f + expf(-gg)));
        }
    }
}

// ---------------------------------------------------------------------------
extern "C" void kernel_launch(void* const* d_in, const int* in_sizes, int n_in,
                              void* d_out, int out_size) {
    const float* x      = (const float*)d_in[0];
    const float* emb    = (const float*)d_in[1];
    const float* A_real = (const float*)d_in[2];
    const float* A_imag = (const float*)d_in[3];
    const float* C      = (const float*)d_in[4];
    const float* log_dt = (const float*)d_in[5];
    const float* B_ssm  = (const float*)d_in[6];
    const float* D_skip = (const float*)d_in[7];
    const float* ln_g   = (const float*)d_in[8];
    const float* ln_b   = (const float*)d_in[9];
    const float* W_out  = (const float*)d_in[10];
    const float* b_out  = (const float*)d_in[11];
    const float* W_film = (const float*)d_in[12];
    const float* b_film = (const float*)d_in[13];
    float* out = (float*)d_out;

    ln_kernel<<<BSZ * LSEQ, 128>>>(x, ln_g, ln_b);
    film_kernel<<<BSZ, 256>>>(emb, W_film, b_film);
    scan_kernel<<<(BSZ * DM) / 8, 128>>>(A_real, A_imag, C, log_dt, B_ssm, D_skip);
    gemm_glu_kernel<<<dim3((BSZ * LSEQ) / GBM, DM / GBN), 256>>>(W_out, b_out, x, out);
}